// round 16
// baseline (speedup 1.0000x reference)
#include <cstdint>
#include <cstddef>
#include <cuda_runtime.h>
#include <cuda_bf16.h>
#include <mma.h>
#include <math.h>

using namespace nvcuda;
typedef __nv_bfloat16 bf16;

// ---------------- problem constants ----------------
#define DIM     384
#define HEADS   6
#define HDIM    64
#define HID     96
#define BB      2
#define NMID    1728
#define NTOK    15768
#define NHIGH   13824
#define NMIDEND 15552
#define MROWS   (BB*NTOK)         // 31536

// weight arena offsets (bf16 elements), [K,N] layout (off+aw interleaved to N=288)
#define WOFF_VAL   0
#define WOFF_OFFAW 147456
#define WOFF_OUT   258048
#define WOFF_FC1   405504
#define WOFF_FC2   442368
#define WTOTAL     479232

// ---------------- scratch (device globals) ----------------
__device__ float g_qn   [(size_t)MROWS*DIM];
__device__ float g_out1 [(size_t)MROWS*DIM];
__device__ float g_offaw[(size_t)MROWS*288];
__device__ float g_val_f[(size_t)MROWS*DIM];     // value in fp32 (feeds f32x2 FMA)
__device__ float g_bias288[288];
__device__ bf16  g_aq_b [(size_t)MROWS*DIM];
__device__ bf16  g_af_b [(size_t)MROWS*DIM];
__device__ bf16  g_dout_b[(size_t)MROWS*DIM];
__device__ bf16  g_xf_b [(size_t)MROWS*HID];
__device__ bf16  g_xg_b [(size_t)MROWS*HID];
__device__ bf16  g_wb   [WTOTAL];

// ---------------- helpers ----------------
__device__ __forceinline__ float2 warp_sum2(float a, float b) {
    #pragma unroll
    for (int o = 16; o > 0; o >>= 1) {
        a += __shfl_xor_sync(0xffffffffu, a, o);
        b += __shfl_xor_sync(0xffffffffu, b, o);
    }
    return make_float2(a, b);
}
__device__ __forceinline__ uint32_t pack_bf16x2(float a, float b) {
    __nv_bfloat162 p = __floats2bfloat162_rn(a, b);
    return *reinterpret_cast<uint32_t*>(&p);
}
__device__ __forceinline__ unsigned long long dup_f32x2(float w) {
    uint32_t wb_ = __float_as_uint(w);
    unsigned long long v;
    asm("mov.b64 %0, {%1, %2};" : "=l"(v) : "r"(wb_), "r"(wb_));
    return v;
}
__device__ __forceinline__ void fma_f32x2(unsigned long long& acc,
                                          unsigned long long a, unsigned long long b) {
    asm("fma.rn.f32x2 %0, %1, %2, %0;" : "+l"(acc) : "l"(a), "l"(b));
}
__device__ __forceinline__ float2 unpack_f32x2(unsigned long long v) {
    float x, y;
    asm("mov.b64 {%0, %1}, %2;" : "=f"(x), "=f"(y) : "l"(v));
    return make_float2(x, y);
}

// ---------------- K1: build q (+feat), fused LN chain + weight convert ----------
__global__ void __launch_bounds__(256) prep_kernel(
        const float* __restrict__ query, const float* __restrict__ feat,
        const float* __restrict__ qw, const float* __restrict__ qb,
        const float* __restrict__ fw, const float* __restrict__ fb,
        const float* __restrict__ eqw, const float* __restrict__ eqb,
        const float* __restrict__ efw, const float* __restrict__ efb,
        float* __restrict__ qn_o, bf16* __restrict__ aq_o, bf16* __restrict__ af_o,
        const float* __restrict__ vw, const float* __restrict__ ow,
        const float* __restrict__ aww, const float* __restrict__ outw,
        const float* __restrict__ f1w, const float* __restrict__ f2w,
        const float* __restrict__ offb, const float* __restrict__ awb,
        bf16* __restrict__ wdst, float* __restrict__ bias288)
{
    // weight convert tail (grid-stride over whole grid; <=1 iter/thread)
    {
        int gid = blockIdx.x * 256 + threadIdx.x;
        if (gid < 288) bias288[gid] = (gid < 216) ? offb[gid] : awb[gid - 216];
        int stride = gridDim.x * 256;
        for (int i = gid; i < WTOTAL; i += stride) {
            float v;
            if      (i < WOFF_OFFAW) v = vw[i];
            else if (i < WOFF_OUT) {
                int rel = i - WOFF_OFFAW;
                int k = rel / 288, j = rel % 288;
                v = (j < 216) ? ow[k * 216 + j] : aww[k * 72 + (j - 216)];
            }
            else if (i < WOFF_FC1) v = outw[i - WOFF_OUT];
            else if (i < WOFF_FC2) v = f1w[i - WOFF_FC1];
            else                   v = f2w[i - WOFF_FC2];
            wdst[i] = __float2bfloat16(v);
        }
    }

    int row = blockIdx.x * 8 + (threadIdx.x >> 5);
    if (row >= MROWS) return;
    int lane = threadIdx.x & 31;
    int b = row / NTOK, t = row % NTOK;

    float x[12];
    float s = 0.f, ss = 0.f;
    const bool addf = (t >= NHIGH && t < NMIDEND);
    const float* qrow = query + (size_t)row * DIM;
    const float* frow = addf ? feat + ((size_t)b * NMID + (t - NHIGH)) * DIM : nullptr;
    #pragma unroll
    for (int i = 0; i < 3; i++) {
        int c = (lane + i * 32) * 4;
        float4 v = *(const float4*)&qrow[c];
        if (addf) {
            float4 f = *(const float4*)&frow[c];
            v.x += f.x; v.y += f.y; v.z += f.z; v.w += f.w;
        }
        x[i*4+0] = v.x; x[i*4+1] = v.y; x[i*4+2] = v.z; x[i*4+3] = v.w;
        s += v.x + v.y + v.z + v.w;
        ss += v.x*v.x + v.y*v.y + v.z*v.z + v.w*v.w;
    }
    float2 r = warp_sum2(s, ss);
    float m  = r.x * (1.f / DIM);
    float rs = rsqrtf(r.y * (1.f / DIM) - m * m + 1e-6f);

    float qv[12], fv[12];
    float s1 = 0.f, ss1 = 0.f, s2 = 0.f, ss2 = 0.f;
    #pragma unroll
    for (int i = 0; i < 3; i++) {
        int c = (lane + i * 32) * 4;
        float4 qwv = *(const float4*)&qw[c];
        float4 qbv = *(const float4*)&qb[c];
        float4 fwv = *(const float4*)&fw[c];
        float4 fbv = *(const float4*)&fb[c];
        float4 o;
        #pragma unroll
        for (int j = 0; j < 4; j++) {
            float xn = (x[i*4+j] - m) * rs;
            float qq = xn * ((&qwv.x)[j]) + ((&qbv.x)[j]);
            float ff = xn * ((&fwv.x)[j]) + ((&fbv.x)[j]);
            qv[i*4+j] = qq; fv[i*4+j] = ff;
            (&o.x)[j] = qq;
            s1 += qq; ss1 += qq*qq;
            s2 += ff; ss2 += ff*ff;
        }
        *(float4*)&qn_o[(size_t)row * DIM + c] = o;
    }
    float2 r1 = warp_sum2(s1, ss1);
    float m1  = r1.x * (1.f / DIM);
    float rs1 = rsqrtf(r1.y * (1.f / DIM) - m1 * m1 + 1e-6f);
    float2 r2 = warp_sum2(s2, ss2);
    float m2  = r2.x * (1.f / DIM);
    float rs2 = rsqrtf(r2.y * (1.f / DIM) - m2 * m2 + 1e-6f);
    #pragma unroll
    for (int i = 0; i < 3; i++) {
        int c = (lane + i * 32) * 4;
        float4 ewv = *(const float4*)&eqw[c];
        float4 ebv = *(const float4*)&eqb[c];
        float4 fwv = *(const float4*)&efw[c];
        float4 fbv = *(const float4*)&efb[c];
        float aqv[4], afv[4];
        #pragma unroll
        for (int j = 0; j < 4; j++) {
            aqv[j] = (qv[i*4+j] - m1) * rs1 * ((&ewv.x)[j]) + ((&ebv.x)[j]);
            afv[j] = (fv[i*4+j] - m2) * rs2 * ((&fwv.x)[j]) + ((&fbv.x)[j]);
        }
        uint2 pa, pf;
        pa.x = pack_bf16x2(aqv[0], aqv[1]); pa.y = pack_bf16x2(aqv[2], aqv[3]);
        pf.x = pack_bf16x2(afv[0], afv[1]); pf.y = pack_bf16x2(afv[2], afv[3]);
        *(uint2*)&aq_o[(size_t)row * DIM + c] = pa;
        *(uint2*)&af_o[(size_t)row * DIM + c] = pf;
    }
}

// ---------------- generic LN (fp32 in -> bf16 out) — warp per row, float4 -----
__global__ void __launch_bounds__(256) ln_kernel(
        const float* __restrict__ xin, const float* __restrict__ w,
        const float* __restrict__ bws, bf16* __restrict__ yo)
{
    int row = blockIdx.x * 8 + (threadIdx.x >> 5);
    if (row >= MROWS) return;
    int lane = threadIdx.x & 31;
    float x[12]; float s = 0.f, ss = 0.f;
    const float* xr = xin + (size_t)row * DIM;
    #pragma unroll
    for (int i = 0; i < 3; i++) {
        int c = (lane + i * 32) * 4;
        float4 v = *(const float4*)&xr[c];
        x[i*4+0] = v.x; x[i*4+1] = v.y; x[i*4+2] = v.z; x[i*4+3] = v.w;
        s += v.x + v.y + v.z + v.w;
        ss += v.x*v.x + v.y*v.y + v.z*v.z + v.w*v.w;
    }
    float2 r = warp_sum2(s, ss);
    float m  = r.x * (1.f / DIM);
    float rs = rsqrtf(r.y * (1.f / DIM) - m * m + 1e-6f);
    #pragma unroll
    for (int i = 0; i < 3; i++) {
        int c = (lane + i * 32) * 4;
        float4 wv = *(const float4*)&w[c];
        float4 bv = *(const float4*)&bws[c];
        float y0 = (x[i*4+0] - m) * rs * wv.x + bv.x;
        float y1 = (x[i*4+1] - m) * rs * wv.y + bv.y;
        float y2 = (x[i*4+2] - m) * rs * wv.z + bv.z;
        float y3 = (x[i*4+3] - m) * rs * wv.w + bv.w;
        uint2 p;
        p.x = pack_bf16x2(y0, y1); p.y = pack_bf16x2(y2, y3);
        *(uint2*)&yo[(size_t)row * DIM + c] = p;
    }
}

// ---------------- bf16 wmma GEMM core, 128x96 tile, 8 warps (32x48 each) ------
template<bool RESID>
__device__ __forceinline__ void gemm_core(
        const bf16* __restrict__ A, const bf16* __restrict__ W,
        const float* __restrict__ bias, const float* __restrict__ resid,
        void* __restrict__ Cout, int M, int N, int K,
        int row0, int col0, bool outbf, char* sraw)
{
    constexpr int BM = 128, BK = 32;
    constexpr int AP = 40, BP = 104, CP = 100;
    bf16* As = (bf16*)sraw;
    bf16* Bs = (bf16*)(sraw + 2 * BM * AP * (int)sizeof(bf16));
    float* Cs = (float*)sraw;

    int tid = threadIdx.x;
    int wid = tid >> 5, wm = wid & 3, wn = wid >> 2;

    const int arow = tid >> 2, acq = (tid & 3) * 8;
    const int br0 = tid / 12,  bc0 = (tid % 12) * 8;
    const int idx2 = tid + 256;
    const int br1 = idx2 / 12, bc1 = (idx2 % 12) * 8;
    const bool haveB1 = (tid < 128);
    const uint4 z4 = make_uint4(0, 0, 0, 0);

    uint4 ra0, ra1, rb0, rb1;
    #define LDG_TILE(K0) do { \
        int r0_ = row0 + arow, r1_ = row0 + arow + 64; \
        ra0 = (r0_ < M) ? *(const uint4*)&A[(size_t)r0_ * K + (K0) + acq] : z4; \
        ra1 = (r1_ < M) ? *(const uint4*)&A[(size_t)r1_ * K + (K0) + acq] : z4; \
        rb0 = *(const uint4*)&W[(size_t)((K0) + br0) * N + col0 + bc0]; \
        if (haveB1) rb1 = *(const uint4*)&W[(size_t)((K0) + br1) * N + col0 + bc1]; \
    } while (0)
    #define STS_TILE(BUF) do { \
        *(uint4*)&As[(BUF) * BM * AP + arow * AP + acq]        = ra0; \
        *(uint4*)&As[(BUF) * BM * AP + (arow + 64) * AP + acq] = ra1; \
        *(uint4*)&Bs[(BUF) * BK * BP + br0 * BP + bc0]         = rb0; \
        if (haveB1) *(uint4*)&Bs[(BUF) * BK * BP + br1 * BP + bc1] = rb1; \
    } while (0)

    wmma::fragment<wmma::accumulator, 16, 16, 16, float> acc[2][3];
    #pragma unroll
    for (int i = 0; i < 2; i++)
        #pragma unroll
        for (int j = 0; j < 3; j++)
            wmma::fill_fragment(acc[i][j], 0.f);

    const int nk = K / BK;
    LDG_TILE(0);
    STS_TILE(0);
    __syncthreads();

    for (int t = 0; t < nk; t++) {
        if (t + 1 < nk) LDG_TILE((t + 1) * BK);
        const bf16* Ab = As + (t & 1) * BM * AP;
        const bf16* Bb = Bs + (t & 1) * BK * BP;
        #pragma unroll
        for (int ks = 0; ks < 2; ks++) {
            wmma::fragment<wmma::matrix_a, 16, 16, 16, bf16, wmma::row_major> fa[2];
            wmma::fragment<wmma::matrix_b, 16, 16, 16, bf16, wmma::row_major> fb[3];
            #pragma unroll
            for (int i = 0; i < 2; i++)
                wmma::load_matrix_sync(fa[i], &Ab[(wm * 32 + i * 16) * AP + ks * 16], AP);
            #pragma unroll
            for (int j = 0; j < 3; j++)
                wmma::load_matrix_sync(fb[j], &Bb[(ks * 16) * BP + wn * 48 + j * 16], BP);
            #pragma unroll
            for (int i = 0; i < 2; i++)
                #pragma unroll
                for (int j = 0; j < 3; j++)
                    wmma::mma_sync(acc[i][j], fa[i], fb[j], acc[i][j]);
        }
        if (t + 1 < nk) STS_TILE((t + 1) & 1);
        __syncthreads();
    }

    #pragma unroll
    for (int i = 0; i < 2; i++)
        #pragma unroll
        for (int j = 0; j < 3; j++)
            wmma::store_matrix_sync(&Cs[(wm * 32 + i * 16) * CP + wn * 48 + j * 16],
                                    acc[i][j], CP, wmma::mem_row_major);
    __syncthreads();
    #pragma unroll
    for (int it = 0; it < 12; it++) {
        int idx = tid + it * 256;
        int r = idx / 24, cq = (idx % 24) * 4;
        int gr = row0 + r, gc = col0 + cq;
        if (gr < M) {
            float4 v = *(const float4*)&Cs[r * CP + cq];
            float4 bv = *(const float4*)&bias[gc];
            v.x += bv.x; v.y += bv.y; v.z += bv.z; v.w += bv.w;
            if (RESID) {
                float4 rv = *(const float4*)&resid[(size_t)gr * N + gc];
                v.x += rv.x; v.y += rv.y; v.z += rv.z; v.w += rv.w;
            }
            if (outbf) {
                uint2 p;
                p.x = pack_bf16x2(v.x, v.y);
                p.y = pack_bf16x2(v.z, v.w);
                *(uint2*)((bf16*)Cout + (size_t)gr * N + gc) = p;
            } else {
                *(float4*)((float*)Cout + (size_t)gr * N + gc) = v;
            }
        }
    }
    #undef LDG_TILE
    #undef STS_TILE
}
#define GEMM_SMEM 51200

template<bool RESID, bool OUTBF>
__global__ void __launch_bounds__(256, 2) gemm_bf16_kernel(
        const bf16* __restrict__ A, const bf16* __restrict__ W,
        const float* __restrict__ bias, const float* __restrict__ resid,
        void* __restrict__ Cout, int M, int N, int K)
{
    extern __shared__ __align__(16) char sraw[];
    gemm_core<RESID>(A, W, bias, resid, Cout, M, N, K,
                     blockIdx.y * 128, blockIdx.x * 96, OUTBF, sraw);
}

// dual-problem GEMM: blockIdx.x < split -> problem 0, else problem 1 (both fp32 out)
__global__ void __launch_bounds__(256, 2) gemm_dual_kernel(
        const bf16* __restrict__ A0, const bf16* __restrict__ W0,
        const float* __restrict__ b0, void* __restrict__ C0, int N0,
        const bf16* __restrict__ A1, const bf16* __restrict__ W1,
        const float* __restrict__ b1, void* __restrict__ C1, int N1,
        int M, int K, int split)
{
    extern __shared__ __align__(16) char sraw[];
    if ((int)blockIdx.x < split)
        gemm_core<false>(A0, W0, b0, nullptr, C0, M, N0, K,
                         blockIdx.y * 128, blockIdx.x * 96, false, sraw);
    else
        gemm_core<false>(A1, W1, b1, nullptr, C1, M, N1, K,
                         blockIdx.y * 128, (blockIdx.x - split) * 96, false, sraw);
}

// ---------------- deformable sampling v9: fp32 value, pure f32x2 FMA ----------
// per point per lane: 1 LDS.128 + 4 ld.global.v2.b64 + 2 dup + 8 FMA2, no unpack.
__global__ void __launch_bounds__(256) deform_kernel(
        const float* __restrict__ offaw,
        const float* __restrict__ value, bf16* __restrict__ out)
{
    const unsigned FULL = 0xffffffffu;
    __shared__ __align__(16) float4 s_pt[8][12][4];   // 6 KB
    int wslot = threadIdx.x >> 5;
    int gw   = (blockIdx.x * blockDim.x + threadIdx.x) >> 5;
    int lane = threadIdx.x & 31;
    if (gw >= MROWS * HEADS) return;
    int h  = gw % HEADS;
    int bq = gw / HEADS;
    int q  = bq % NTOK;
    int b  = bq / NTOK;

    float rd, rx, ry;
    {
        int S, loc;
        if (q < NHIGH)        { S = 24; loc = q; }
        else if (q < NMIDEND) { S = 12; loc = q - NHIGH; }
        else                  { S = 6;  loc = q - NMIDEND; }
        int d = loc / (S * S), y = (loc / S) % S, x = loc % S;
        float inv = 1.f / (float)S;
        rd = (d + 0.5f) * inv; ry = (y + 0.5f) * inv; rx = (x + 0.5f) * inv;
    }

    // ---- phase 1: lane pp handles point pp; softmax fused; build smem table ----
    {
        int pp = (lane < 12) ? lane : 0;
        float logit = offaw[(size_t)bq * 288 + 216 + h * 12 + pp];
        float lm = (lane < 12) ? logit : -1e30f;
        #pragma unroll
        for (int o = 16; o > 0; o >>= 1) lm = fmaxf(lm, __shfl_xor_sync(FULL, lm, o));
        float e = expf(logit - lm);
        float es = (lane < 12) ? e : 0.f;
        #pragma unroll
        for (int o = 16; o > 0; o >>= 1) es += __shfl_xor_sync(FULL, es, o);
        float a = e / es;

        if (lane < 12) {
            int l = pp >> 2;
            int S  = (l == 0) ? 24 : ((l == 1) ? 12 : 6);
            int st = (l == 0) ? 0  : ((l == 1) ? NHIGH : NMIDEND);
            const float* o = offaw + (size_t)bq * 288 + h * 36 + pp * 3;
            float pd = rd * S + o[0] - 0.5f;
            float px = rx * S + o[1] - 0.5f;
            float py = ry * S + o[2] - 0.5f;
            float fd = floorf(pd), fx = floorf(px), fy = floorf(py);
            int d0 = (int)fd, x0 = (int)fx, y0 = (int)fy;
            int d1 = d0 + 1, x1 = x0 + 1, y1 = y0 + 1;
            float wd1 = pd - fd, wx1 = px - fx, wy1 = py - fy;
            float wD0 = a * (1.f - wd1) * ((d0 >= 0 && d0 < S) ? 1.f : 0.f);
            float wD1 = a * wd1        * ((d1 >= 0 && d1 < S) ? 1.f : 0.f);
            float wY0 = (1.f - wy1) * ((y0 >= 0 && y0 < S) ? 1.f : 0.f);
            float wY1 = wy1         * ((y1 >= 0 && y1 < S) ? 1.f : 0.f);
            float wX0 = (1.f - wx1) * ((x0 >= 0 && x0 < S) ? 1.f : 0.f);
            float wX1 = wx1         * ((x1 >= 0 && x1 < S) ? 1.f : 0.f);
            int cd0 = min(max(d0, 0), S - 1), cd1 = min(max(d1, 0), S - 1);
            int cy0 = min(max(y0, 0), S - 1), cy1 = min(max(y1, 0), S - 1);
            int cx0 = min(max(x0, 0), S - 1);
            int cx1 = min(max(x1, 0), S - 1);
            // byte offsets: element index * DIM * 4 bytes = idx * 1536
            int c0b = cx0 * (DIM * 4), c1b = cx1 * (DIM * 4);
            int ib[4];
            ib[0] = (st + cd0 * S * S + cy0 * S) * (DIM * 4);
            ib[1] = (st + cd0 * S * S + cy1 * S) * (DIM * 4);
            ib[2] = (st + cd1 * S * S + cy0 * S) * (DIM * 4);
            ib[3] = (st + cd1 * S * S + cy1 * S) * (DIM * 4);
            float wdy[4];
            wdy[0] = wD0 * wY0; wdy[1] = wD0 * wY1;
            wdy[2] = wD1 * wY0; wdy[3] = wD1 * wY1;
            #pragma unroll
            for (int cg = 0; cg < 4; cg++) {
                float4 ent;
                ent.x = wdy[cg] * wX0;
                ent.y = wdy[cg] * wX1;
                ent.z = __int_as_float(ib[cg] + c0b);
                ent.w = __int_as_float(ib[cg] + c1b);
                s_pt[wslot][pp][cg] = ent;
            }
        }
    }
    __syncwarp();

    // ---- phase 2: per point: 1 LDS.128 + 4 ld.v2.b64, f32x2 FMA directly ----
    const int cg  = lane >> 3;
    const int ch8 = (lane & 7) * 8;
    const char* vbb = (const char*)(value + (size_t)b * NTOK * DIM + h * HDIM + ch8);

    unsigned long long a01 = 0ull, a23 = 0ull, a45 = 0ull, a67 = 0ull;
    #pragma unroll
    for (int p = 0; p < 12; p++) {
        float4 ent = s_pt[wslot][p][cg];
        {
            const char* base = vbb + __float_as_int(ent.z);
            ulonglong2 r0 = *(const ulonglong2*)base;
            ulonglong2 r1 = *(const ulonglong2*)(base + 16);
            unsigned long long w2 = dup_f32x2(ent.x);
            fma_f32x2(a01, r0.x, w2);
            fma_f32x2(a23, r0.y, w2);
            fma_f32x2(a45, r1.x, w2);
            fma_f32x2(a67, r1.y, w2);
        }
        {
            const char* base = vbb + __float_as_int(ent.w);
            ulonglong2 r0 = *(const ulonglong2*)base;
            ulonglong2 r1 = *(const ulonglong2*)(base + 16);
            unsigned long long w2 = dup_f32x2(ent.y);
            fma_f32x2(a01, r0.x, w2);
            fma_f32x2(a23, r0.y, w2);
            fma_f32x2(a45, r1.x, w2);
            fma_f32x2(a67, r1.y, w2);
        }
    }
    float2 p01 = unpack_f32x2(a01);
    float2 p23 = unpack_f32x2(a23);
    float2 p45 = unpack_f32x2(a45);
    float2 p67 = unpack_f32x2(a67);
    float a0 = p01.x, a1 = p01.y, a2 = p23.x, a3 = p23.y;
    float a4 = p45.x, a5 = p45.y, a6 = p67.x, a7 = p67.y;
    #pragma unroll
    for (int o = 16; o >= 8; o >>= 1) {
        a0 += __shfl_down_sync(FULL, a0, o);
        a1 += __shfl_down_sync(FULL, a1, o);
        a2 += __shfl_down_sync(FULL, a2, o);
        a3 += __shfl_down_sync(FULL, a3, o);
        a4 += __shfl_down_sync(FULL, a4, o);
        a5 += __shfl_down_sync(FULL, a5, o);
        a6 += __shfl_down_sync(FULL, a6, o);
        a7 += __shfl_down_sync(FULL, a7, o);
    }
    if (lane < 8) {
        uint4 pkt;
        pkt.x = pack_bf16x2(a0, a1);
        pkt.y = pack_bf16x2(a2, a3);
        pkt.z = pack_bf16x2(a4, a5);
        pkt.w = pack_bf16x2(a6, a7);
        *(uint4*)(out + (size_t)bq * DIM + h * HDIM + ch8) = pkt;
    }
}

// ---------------- depthwise 3x3x3 conv + GELU: 48 voxels/block, 8ch/thread ----
__global__ void __launch_bounds__(576) dwconv_gelu_kernel(
        const bf16* __restrict__ x, const float* __restrict__ w,
        const float* __restrict__ bias, bf16* __restrict__ y)
{
    __shared__ float sw[27 * HID];
    int tid = threadIdx.x;                 // 576
    for (int i = tid; i < 27 * HID; i += 576) sw[i] = w[i];
    __syncthreads();

    int c8  = (tid % 12) * 8;
    int vox = tid / 12;
    int vlin = blockIdx.x * 48 + vox;
    int b = vlin / NTOK, v = vlin % NTOK;

    int S, base;
    if (v < NHIGH)        { S = 24; base = 0; }
    else if (v < NMIDEND) { S = 12; base = NHIGH; }
    else                  { S = 6;  base = NMIDEND; }
    int loc = v - base;
    int d = loc / (S * S), yy = (loc / S) % S, xx = loc % S;

    const bf16* xb = x + ((size_t)b * NTOK + base) * HID + c8;
    float4 bv0 = *(const float4*)&bias[c8];
    float4 bv1 = *(const float4*)&bias[c8 + 4];
    float a0 = bv0.x, a1 = bv0.y, a2 = bv0.z, a3 = bv0.w;
    float a4 = bv1.x, a5 = bv1.y, a6 = bv1.z, a7 = bv1.w;
    #pragma unroll
    for (int kd = 0; kd < 3; kd++) {
        int di = d + kd - 1;
        if (di < 0 || di >= S) continue;
        #pragma unroll
        for (int kh = 0; kh < 3; kh++) {
            int yi = yy + kh - 1;
            if (yi < 0 || yi >= S) continue;
            #pragma unroll
            for (int kw = 0; kw < 3; kw++) {
                int xi = xx + kw - 1;
                if (xi < 0 || xi >= S) continue;
                uint4 raw = *(const uint4*)(xb + (size_t)((di * S + yi) * S + xi) * HID);
                float2 va = __bfloat1622float2(*(const __nv_bfloat162*)&raw.x);
                float2 vb2 = __bfloat1622float2(*(const __nv_bfloat162*)&raw.y);
                float2 vc = __bfloat1622float2(*(const __nv_bfloat162*)&raw.z);
                float2 vd = __bfloat1622float2(*(const __nv_bfloat162*)&raw.w);
                const float* wp = &sw[((kd * 3 + kh) * 3 + kw) * HID + c8];
                float4 wv0 = *(const float4*)wp;
                float4 wv1 = *(const float4*)(wp + 4);
                a0 += wv0.x * va.x;  a1 += wv0.y * va.y;
                a2 += wv0.z * vb2.x; a3 += wv0.w * vb2.y;
                a4 += wv1.x * vc.x;  a5 += wv1.y * vc.y;
                a6 += wv1.z * vd.x;  a7 += wv1.w * vd.y;
            }
        }
    }
    const float ISQ2 = 0.70710678118654752f;
    float g0 = 0.5f * a0 * (1.f + erff(a0 * ISQ2));
    float g1 = 0.5f * a1 * (1.f + erff(a1 * ISQ2));
    float g2 = 0.5f * a2 * (1.f + erff(a2 * ISQ2));
    float g3 = 0.5f * a3 * (1.f + erff(a3 * ISQ2));
    float g4 = 0.5f * a4 * (1.f + erff(a4 * ISQ2));
    float g5 = 0.5f * a5 * (1.f + erff(a5 * ISQ2));
    float g6 = 0.5f * a6 * (1.f + erff(a6 * ISQ2));
    float g7 = 0.5f * a7 * (1.f + erff(a7 * ISQ2));
    uint4 pkt;
    pkt.x = pack_bf16x2(g0, g1);
    pkt.y = pack_bf16x2(g2, g3);
    pkt.z = pack_bf16x2(g4, g5);
    pkt.w = pack_bf16x2(g6, g7);
    *(uint4*)(y + ((size_t)b * NTOK + v) * HID + c8) = pkt;
}

// ---------------- launch ----------------
static void* sym_addr(const void* sym) {
    void* p = nullptr;
    cudaGetSymbolAddress(&p, sym);
    return p;
}

extern "C" void kernel_launch(void* const* d_in, const int* in_sizes, int n_in,
                              void* d_out, int out_size)
{
    const float* query = (const float*)d_in[0];
    const float* feat  = (const float*)d_in[2];
    int wb = n_in - 24;
    const float* qnorm_w    = (const float*)d_in[wb + 0];
    const float* qnorm_b    = (const float*)d_in[wb + 1];
    const float* fnorm_w    = (const float*)d_in[wb + 2];
    const float* fnorm_b    = (const float*)d_in[wb + 3];
    const float* ext_qnorm_w= (const float*)d_in[wb + 4];
    const float* ext_qnorm_b= (const float*)d_in[wb + 5];
    const float* ext_fnorm_w= (const float*)d_in[wb + 6];
    const float* ext_fnorm_b= (const float*)d_in[wb + 7];
    const float* ffn_norm_w = (const float*)d_in[wb + 8];
    const float* ffn_norm_b = (const float*)d_in[wb + 9];
    const float* off_w      = (const float*)d_in[wb + 10];
    const float* off_b      = (const float*)d_in[wb + 11];
    const float* aw_w       = (const float*)d_in[wb + 12];
    const float* aw_b       = (const float*)d_in[wb + 13];
    const float* val_w      = (const float*)d_in[wb + 14];
    const float* val_b      = (const float*)d_in[wb + 15];
    const float* out_w      = (const float*)d_in[wb + 16];
    const float* out_b      = (const float*)d_in[wb + 17];
    const float* fc1_w      = (const float*)d_in[wb + 18];
    const float* fc1_b      = (const float*)d_in[wb + 19];
    const float* dw_w       = (const float*)d_in[wb + 20];
    const float* dw_b       = (const float*)d_in[wb + 21];
    const float* fc2_w      = (const float*)d_in[wb + 22];
    const float* fc2_b      = (const float*)d_in[wb + 23];

    float* qn    = (float*)sym_addr(g_qn);
    float* out1  = (float*)sym_addr(g_out1);
    float* offaw = (float*)sym_addr(g_offaw);
    float* valf  = (float*)sym_addr(g_val_f);
    float* bias288 = (float*)sym_addr(g_bias288);
    bf16* aqb    = (bf16*)sym_addr(g_aq_b);
    bf16* afb    = (bf16*)sym_addr(g_af_b);
    bf16* doutb  = (bf16*)sym_addr(g_dout_b);
    bf16* xfb    = (bf16*)sym_addr(g_xf_b);
    bf16* xgb    = (bf16*)sym_addr(g_xg_b);
    bf16* wbf    = (bf16*)sym_addr(g_wb);
    float* outp  = (float*)d_out;

    cudaFuncSetAttribute(gemm_bf16_kernel<false, true>,  cudaFuncAttributeMaxDynamicSharedMemorySize, GEMM_SMEM);
    cudaFuncSetAttribute(gemm_bf16_kernel<false, false>, cudaFuncAttributeMaxDynamicSharedMemorySize, GEMM_SMEM);
    cudaFuncSetAttribute(gemm_bf16_kernel<true,  false>, cudaFuncAttributeMaxDynamicSharedMemorySize, GEMM_SMEM);
    cudaFuncSetAttribute(gemm_dual_kernel, cudaFuncAttributeMaxDynamicSharedMemorySize, GEMM_SMEM);

    const int M = MROWS;
    int gy = (M + 127) / 128;
    int grow = (M + 7) / 8;

    // 1) q build + LN chain (warp per row) + fused weight convert
    prep_kernel<<<grow, 256>>>(query, feat, qnorm_w, qnorm_b, fnorm_w, fnorm_b,
                               ext_qnorm_w, ext_qnorm_b, ext_fnorm_w, ext_fnorm_b,
                               qn, aqb, afb,
                               val_w, off_w, aw_w, out_w, fc1_w, fc2_w,
                               off_b, aw_b, wbf, bias288);
    // 2+3) fused: value = af @ val_w + val_b (fp32) AND offaw = aq @ [off|aw]_w + bias (fp32)
    gemm_dual_kernel<<<dim3(7, gy), 256, GEMM_SMEM>>>(
        afb, wbf + WOFF_VAL, val_b, valf, 384,
        aqb, wbf + WOFF_OFFAW, bias288, offaw, 288,
        M, 384, 4);
    // 4) deformable sampling (softmax fused, fp32 value, f32x2 FMA)
    {
        int warps = MROWS * HEADS;
        int blocks = (warps + 7) / 8;
        deform_kernel<<<blocks, 256>>>(offaw, valf, doutb);
    }
    // 5) out1 = qn + dout @ out_w + out_b (fp32)
    gemm_bf16_kernel<true, false><<<dim3(4, gy), 256, GEMM_SMEM>>>(doutb, wbf + WOFF_OUT, out_b, qn, out1, M, 384, 384);
    // 6) t = LN(out1, ffn_norm) -> bf16
    ln_kernel<<<grow, 256>>>(out1, ffn_norm_w, ffn_norm_b, aqb);
    // 7) x = t @ fc1_w + fc1_b  (bf16 out)
    gemm_bf16_kernel<false, true><<<dim3(1, gy), 256, GEMM_SMEM>>>(aqb, wbf + WOFF_FC1, fc1_b, nullptr, xfb, M, 96, 384);
    // 8) depthwise conv + GELU (bf16 out, 48 voxels/block)
    dwconv_gelu_kernel<<<MROWS / 48, 576>>>(xfb, dw_w, dw_b, xgb);
    // 9) out = out1 + xg @ fc2_w + fc2_b (fp32)
    gemm_bf16_kernel<true, false><<<dim3(4, gy), 256, GEMM_SMEM>>>(xgb, wbf + WOFF_FC2, fc2_b, out1, outp, M, 384, 96);
}

// round 17
// speedup vs baseline: 1.3135x; 1.3135x over previous
#include <cstdint>
#include <cstddef>
#include <cuda_runtime.h>
#include <cuda_bf16.h>
#include <mma.h>
#include <math.h>

using namespace nvcuda;
typedef __nv_bfloat16 bf16;

// ---------------- problem constants ----------------
#define DIM     384
#define HEADS   6
#define HDIM    64
#define HID     96
#define BB      2
#define NMID    1728
#define NTOK    15768
#define NHIGH   13824
#define NMIDEND 15552
#define MROWS   (BB*NTOK)         // 31536

// weight arena offsets (bf16 elements), [K,N] layout (off+aw interleaved to N=288)
#define WOFF_VAL   0
#define WOFF_OFFAW 147456
#define WOFF_OUT   258048
#define WOFF_FC1   405504
#define WOFF_FC2   442368
#define WTOTAL     479232

// ---------------- scratch (device globals) ----------------
__device__ float g_qn   [(size_t)MROWS*DIM];
__device__ float g_out1 [(size_t)MROWS*DIM];
__device__ float g_offaw[(size_t)MROWS*288];
__device__ float g_bias288[288];
__device__ bf16  g_aq_b [(size_t)MROWS*DIM];
__device__ bf16  g_af_b [(size_t)MROWS*DIM];
__device__ bf16  g_val_b[(size_t)MROWS*DIM];
__device__ bf16  g_dout_b[(size_t)MROWS*DIM];
__device__ bf16  g_xf_b [(size_t)MROWS*HID];
__device__ bf16  g_xg_b [(size_t)MROWS*HID];
__device__ bf16  g_wb   [WTOTAL];

// ---------------- helpers ----------------
__device__ __forceinline__ float2 warp_sum2(float a, float b) {
    #pragma unroll
    for (int o = 16; o > 0; o >>= 1) {
        a += __shfl_xor_sync(0xffffffffu, a, o);
        b += __shfl_xor_sync(0xffffffffu, b, o);
    }
    return make_float2(a, b);
}
__device__ __forceinline__ uint32_t pack_bf16x2(float a, float b) {
    __nv_bfloat162 p = __floats2bfloat162_rn(a, b);
    return *reinterpret_cast<uint32_t*>(&p);
}
// packed f32x2 helpers (sm_100-family base PTX)
__device__ __forceinline__ unsigned long long pack2_from_bf16x2(uint32_t raw) {
    uint32_t lo = raw << 16;
    uint32_t hi = raw & 0xffff0000u;
    unsigned long long v;
    asm("mov.b64 %0, {%1, %2};" : "=l"(v) : "r"(lo), "r"(hi));
    return v;
}
__device__ __forceinline__ unsigned long long dup_f32x2(float w) {
    uint32_t wb_ = __float_as_uint(w);
    unsigned long long v;
    asm("mov.b64 %0, {%1, %2};" : "=l"(v) : "r"(wb_), "r"(wb_));
    return v;
}
__device__ __forceinline__ void fma_f32x2(unsigned long long& acc,
                                          unsigned long long a, unsigned long long b) {
    asm("fma.rn.f32x2 %0, %1, %2, %0;" : "+l"(acc) : "l"(a), "l"(b));
}
__device__ __forceinline__ float2 unpack_f32x2(unsigned long long v) {
    float x, y;
    asm("mov.b64 {%0, %1}, %2;" : "=f"(x), "=f"(y) : "l"(v));
    return make_float2(x, y);
}

// ---------------- K1: build q (+feat), fused LN chain + weight convert ----------
__global__ void __launch_bounds__(256) prep_kernel(
        const float* __restrict__ query, const float* __restrict__ feat,
        const float* __restrict__ qw, const float* __restrict__ qb,
        const float* __restrict__ fw, const float* __restrict__ fb,
        const float* __restrict__ eqw, const float* __restrict__ eqb,
        const float* __restrict__ efw, const float* __restrict__ efb,
        float* __restrict__ qn_o, bf16* __restrict__ aq_o, bf16* __restrict__ af_o,
        const float* __restrict__ vw, const float* __restrict__ ow,
        const float* __restrict__ aww, const float* __restrict__ outw,
        const float* __restrict__ f1w, const float* __restrict__ f2w,
        const float* __restrict__ offb, const float* __restrict__ awb,
        bf16* __restrict__ wdst, float* __restrict__ bias288)
{
    // weight convert tail (grid-stride over whole grid; <=1 iter/thread)
    {
        int gid = blockIdx.x * 256 + threadIdx.x;
        if (gid < 288) bias288[gid] = (gid < 216) ? offb[gid] : awb[gid - 216];
        int stride = gridDim.x * 256;
        for (int i = gid; i < WTOTAL; i += stride) {
            float v;
            if      (i < WOFF_OFFAW) v = vw[i];
            else if (i < WOFF_OUT) {
                int rel = i - WOFF_OFFAW;
                int k = rel / 288, j = rel % 288;
                v = (j < 216) ? ow[k * 216 + j] : aww[k * 72 + (j - 216)];
            }
            else if (i < WOFF_FC1) v = outw[i - WOFF_OUT];
            else if (i < WOFF_FC2) v = f1w[i - WOFF_FC1];
            else                   v = f2w[i - WOFF_FC2];
            wdst[i] = __float2bfloat16(v);
        }
    }

    int row = blockIdx.x * 8 + (threadIdx.x >> 5);
    if (row >= MROWS) return;
    int lane = threadIdx.x & 31;
    int b = row / NTOK, t = row % NTOK;

    float x[12];
    float s = 0.f, ss = 0.f;
    const bool addf = (t >= NHIGH && t < NMIDEND);
    const float* qrow = query + (size_t)row * DIM;
    const float* frow = addf ? feat + ((size_t)b * NMID + (t - NHIGH)) * DIM : nullptr;
    #pragma unroll
    for (int i = 0; i < 3; i++) {
        int c = (lane + i * 32) * 4;
        float4 v = *(const float4*)&qrow[c];
        if (addf) {
            float4 f = *(const float4*)&frow[c];
            v.x += f.x; v.y += f.y; v.z += f.z; v.w += f.w;
        }
        x[i*4+0] = v.x; x[i*4+1] = v.y; x[i*4+2] = v.z; x[i*4+3] = v.w;
        s += v.x + v.y + v.z + v.w;
        ss += v.x*v.x + v.y*v.y + v.z*v.z + v.w*v.w;
    }
    float2 r = warp_sum2(s, ss);
    float m  = r.x * (1.f / DIM);
    float rs = rsqrtf(r.y * (1.f / DIM) - m * m + 1e-6f);

    float qv[12], fv[12];
    float s1 = 0.f, ss1 = 0.f, s2 = 0.f, ss2 = 0.f;
    #pragma unroll
    for (int i = 0; i < 3; i++) {
        int c = (lane + i * 32) * 4;
        float4 qwv = *(const float4*)&qw[c];
        float4 qbv = *(const float4*)&qb[c];
        float4 fwv = *(const float4*)&fw[c];
        float4 fbv = *(const float4*)&fb[c];
        float4 o;
        #pragma unroll
        for (int j = 0; j < 4; j++) {
            float xn = (x[i*4+j] - m) * rs;
            float qq = xn * ((&qwv.x)[j]) + ((&qbv.x)[j]);
            float ff = xn * ((&fwv.x)[j]) + ((&fbv.x)[j]);
            qv[i*4+j] = qq; fv[i*4+j] = ff;
            (&o.x)[j] = qq;
            s1 += qq; ss1 += qq*qq;
            s2 += ff; ss2 += ff*ff;
        }
        *(float4*)&qn_o[(size_t)row * DIM + c] = o;
    }
    float2 r1 = warp_sum2(s1, ss1);
    float m1  = r1.x * (1.f / DIM);
    float rs1 = rsqrtf(r1.y * (1.f / DIM) - m1 * m1 + 1e-6f);
    float2 r2 = warp_sum2(s2, ss2);
    float m2  = r2.x * (1.f / DIM);
    float rs2 = rsqrtf(r2.y * (1.f / DIM) - m2 * m2 + 1e-6f);
    #pragma unroll
    for (int i = 0; i < 3; i++) {
        int c = (lane + i * 32) * 4;
        float4 ewv = *(const float4*)&eqw[c];
        float4 ebv = *(const float4*)&eqb[c];
        float4 fwv = *(const float4*)&efw[c];
        float4 fbv = *(const float4*)&efb[c];
        float aqv[4], afv[4];
        #pragma unroll
        for (int j = 0; j < 4; j++) {
            aqv[j] = (qv[i*4+j] - m1) * rs1 * ((&ewv.x)[j]) + ((&ebv.x)[j]);
            afv[j] = (fv[i*4+j] - m2) * rs2 * ((&fwv.x)[j]) + ((&fbv.x)[j]);
        }
        uint2 pa, pf;
        pa.x = pack_bf16x2(aqv[0], aqv[1]); pa.y = pack_bf16x2(aqv[2], aqv[3]);
        pf.x = pack_bf16x2(afv[0], afv[1]); pf.y = pack_bf16x2(afv[2], afv[3]);
        *(uint2*)&aq_o[(size_t)row * DIM + c] = pa;
        *(uint2*)&af_o[(size_t)row * DIM + c] = pf;
    }
}

// ---------------- generic LN (fp32 in -> bf16 out) — warp per row, float4 -----
__global__ void __launch_bounds__(256) ln_kernel(
        const float* __restrict__ xin, const float* __restrict__ w,
        const float* __restrict__ bws, bf16* __restrict__ yo)
{
    int row = blockIdx.x * 8 + (threadIdx.x >> 5);
    if (row >= MROWS) return;
    int lane = threadIdx.x & 31;
    float x[12]; float s = 0.f, ss = 0.f;
    const float* xr = xin + (size_t)row * DIM;
    #pragma unroll
    for (int i = 0; i < 3; i++) {
        int c = (lane + i * 32) * 4;
        float4 v = *(const float4*)&xr[c];
        x[i*4+0] = v.x; x[i*4+1] = v.y; x[i*4+2] = v.z; x[i*4+3] = v.w;
        s += v.x + v.y + v.z + v.w;
        ss += v.x*v.x + v.y*v.y + v.z*v.z + v.w*v.w;
    }
    float2 r = warp_sum2(s, ss);
    float m  = r.x * (1.f / DIM);
    float rs = rsqrtf(r.y * (1.f / DIM) - m * m + 1e-6f);
    #pragma unroll
    for (int i = 0; i < 3; i++) {
        int c = (lane + i * 32) * 4;
        float4 wv = *(const float4*)&w[c];
        float4 bv = *(const float4*)&bws[c];
        float y0 = (x[i*4+0] - m) * rs * wv.x + bv.x;
        float y1 = (x[i*4+1] - m) * rs * wv.y + bv.y;
        float y2 = (x[i*4+2] - m) * rs * wv.z + bv.z;
        float y3 = (x[i*4+3] - m) * rs * wv.w + bv.w;
        uint2 p;
        p.x = pack_bf16x2(y0, y1); p.y = pack_bf16x2(y2, y3);
        *(uint2*)&yo[(size_t)row * DIM + c] = p;
    }
}

// ---------------- bf16 wmma GEMM core, 128x96 tile, 8 warps (32x48 each) ------
template<bool RESID>
__device__ __forceinline__ void gemm_core(
        const bf16* __restrict__ A, const bf16* __restrict__ W,
        const float* __restrict__ bias, const float* __restrict__ resid,
        void* __restrict__ Cout, int M, int N, int K,
        int row0, int col0, bool outbf, char* sraw)
{
    constexpr int BM = 128, BK = 32;
    constexpr int AP = 40, BP = 104, CP = 100;
    bf16* As = (bf16*)sraw;
    bf16* Bs = (bf16*)(sraw + 2 * BM * AP * (int)sizeof(bf16));
    float* Cs = (float*)sraw;

    int tid = threadIdx.x;
    int wid = tid >> 5, wm = wid & 3, wn = wid >> 2;

    const int arow = tid >> 2, acq = (tid & 3) * 8;
    const int br0 = tid / 12,  bc0 = (tid % 12) * 8;
    const int idx2 = tid + 256;
    const int br1 = idx2 / 12, bc1 = (idx2 % 12) * 8;
    const bool haveB1 = (tid < 128);
    const uint4 z4 = make_uint4(0, 0, 0, 0);

    uint4 ra0, ra1, rb0, rb1;
    #define LDG_TILE(K0) do { \
        int r0_ = row0 + arow, r1_ = row0 + arow + 64; \
        ra0 = (r0_ < M) ? *(const uint4*)&A[(size_t)r0_ * K + (K0) + acq] : z4; \
        ra1 = (r1_ < M) ? *(const uint4*)&A[(size_t)r1_ * K + (K0) + acq] : z4; \
        rb0 = *(const uint4*)&W[(size_t)((K0) + br0) * N + col0 + bc0]; \
        if (haveB1) rb1 = *(const uint4*)&W[(size_t)((K0) + br1) * N + col0 + bc1]; \
    } while (0)
    #define STS_TILE(BUF) do { \
        *(uint4*)&As[(BUF) * BM * AP + arow * AP + acq]        = ra0; \
        *(uint4*)&As[(BUF) * BM * AP + (arow + 64) * AP + acq] = ra1; \
        *(uint4*)&Bs[(BUF) * BK * BP + br0 * BP + bc0]         = rb0; \
        if (haveB1) *(uint4*)&Bs[(BUF) * BK * BP + br1 * BP + bc1] = rb1; \
    } while (0)

    wmma::fragment<wmma::accumulator, 16, 16, 16, float> acc[2][3];
    #pragma unroll
    for (int i = 0; i < 2; i++)
        #pragma unroll
        for (int j = 0; j < 3; j++)
            wmma::fill_fragment(acc[i][j], 0.f);

    const int nk = K / BK;
    LDG_TILE(0);
    STS_TILE(0);
    __syncthreads();

    for (int t = 0; t < nk; t++) {
        if (t + 1 < nk) LDG_TILE((t + 1) * BK);
        const bf16* Ab = As + (t & 1) * BM * AP;
        const bf16* Bb = Bs + (t & 1) * BK * BP;
        #pragma unroll
        for (int ks = 0; ks < 2; ks++) {
            wmma::fragment<wmma::matrix_a, 16, 16, 16, bf16, wmma::row_major> fa[2];
            wmma::fragment<wmma::matrix_b, 16, 16, 16, bf16, wmma::row_major> fb[3];
            #pragma unroll
            for (int i = 0; i < 2; i++)
                wmma::load_matrix_sync(fa[i], &Ab[(wm * 32 + i * 16) * AP + ks * 16], AP);
            #pragma unroll
            for (int j = 0; j < 3; j++)
                wmma::load_matrix_sync(fb[j], &Bb[(ks * 16) * BP + wn * 48 + j * 16], BP);
            #pragma unroll
            for (int i = 0; i < 2; i++)
                #pragma unroll
                for (int j = 0; j < 3; j++)
                    wmma::mma_sync(acc[i][j], fa[i], fb[j], acc[i][j]);
        }
        if (t + 1 < nk) STS_TILE((t + 1) & 1);
        __syncthreads();
    }

    #pragma unroll
    for (int i = 0; i < 2; i++)
        #pragma unroll
        for (int j = 0; j < 3; j++)
            wmma::store_matrix_sync(&Cs[(wm * 32 + i * 16) * CP + wn * 48 + j * 16],
                                    acc[i][j], CP, wmma::mem_row_major);
    __syncthreads();
    #pragma unroll
    for (int it = 0; it < 12; it++) {
        int idx = tid + it * 256;
        int r = idx / 24, cq = (idx % 24) * 4;
        int gr = row0 + r, gc = col0 + cq;
        if (gr < M) {
            float4 v = *(const float4*)&Cs[r * CP + cq];
            float4 bv = *(const float4*)&bias[gc];
            v.x += bv.x; v.y += bv.y; v.z += bv.z; v.w += bv.w;
            if (RESID) {
                float4 rv = *(const float4*)&resid[(size_t)gr * N + gc];
                v.x += rv.x; v.y += rv.y; v.z += rv.z; v.w += rv.w;
            }
            if (outbf) {
                uint2 p;
                p.x = pack_bf16x2(v.x, v.y);
                p.y = pack_bf16x2(v.z, v.w);
                *(uint2*)((bf16*)Cout + (size_t)gr * N + gc) = p;
            } else {
                *(float4*)((float*)Cout + (size_t)gr * N + gc) = v;
            }
        }
    }
    #undef LDG_TILE
    #undef STS_TILE
}
#define GEMM_SMEM 51200

template<bool RESID, bool OUTBF>
__global__ void __launch_bounds__(256, 2) gemm_bf16_kernel(
        const bf16* __restrict__ A, const bf16* __restrict__ W,
        const float* __restrict__ bias, const float* __restrict__ resid,
        void* __restrict__ Cout, int M, int N, int K)
{
    extern __shared__ __align__(16) char sraw[];
    gemm_core<RESID>(A, W, bias, resid, Cout, M, N, K,
                     blockIdx.y * 128, blockIdx.x * 96, OUTBF, sraw);
}

// dual-problem GEMM: blockIdx.x < split -> problem 0 (bf16 out), else problem 1 (fp32 out)
__global__ void __launch_bounds__(256, 2) gemm_dual_kernel(
        const bf16* __restrict__ A0, const bf16* __restrict__ W0,
        const float* __restrict__ b0, void* __restrict__ C0, int N0,
        const bf16* __restrict__ A1, const bf16* __restrict__ W1,
        const float* __restrict__ b1, void* __restrict__ C1, int N1,
        int M, int K, int split)
{
    extern __shared__ __align__(16) char sraw[];
    if ((int)blockIdx.x < split)
        gemm_core<false>(A0, W0, b0, nullptr, C0, M, N0, K,
                         blockIdx.y * 128, blockIdx.x * 96, true, sraw);
    else
        gemm_core<false>(A1, W1, b1, nullptr, C1, M, N1, K,
                         blockIdx.y * 128, (blockIdx.x - split) * 96, false, sraw);
}

// ---------------- deformable sampling v8: smem tables + packed f32x2 FMA ------
__global__ void __launch_bounds__(256) deform_kernel(
        const float* __restrict__ offaw,
        const bf16* __restrict__ value, bf16* __restrict__ out)
{
    const unsigned FULL = 0xffffffffu;
    __shared__ __align__(16) float4 s_pt[8][12][4];   // 6 KB
    int wslot = threadIdx.x >> 5;
    int gw   = (blockIdx.x * blockDim.x + threadIdx.x) >> 5;
    int lane = threadIdx.x & 31;
    if (gw >= MROWS * HEADS) return;
    int h  = gw % HEADS;
    int bq = gw / HEADS;
    int q  = bq % NTOK;
    int b  = bq / NTOK;

    float rd, rx, ry;
    {
        int S, loc;
        if (q < NHIGH)        { S = 24; loc = q; }
        else if (q < NMIDEND) { S = 12; loc = q - NHIGH; }
        else                  { S = 6;  loc = q - NMIDEND; }
        int d = loc / (S * S), y = (loc / S) % S, x = loc % S;
        float inv = 1.f / (float)S;
        rd = (d + 0.5f) * inv; ry = (y + 0.5f) * inv; rx = (x + 0.5f) * inv;
    }

    // ---- phase 1: lane pp handles point pp; softmax fused; build smem table ----
    {
        int pp = (lane < 12) ? lane : 0;
        float logit = offaw[(size_t)bq * 288 + 216 + h * 12 + pp];
        float lm = (lane < 12) ? logit : -1e30f;
        #pragma unroll
        for (int o = 16; o > 0; o >>= 1) lm = fmaxf(lm, __shfl_xor_sync(FULL, lm, o));
        float e = expf(logit - lm);
        float es = (lane < 12) ? e : 0.f;
        #pragma unroll
        for (int o = 16; o > 0; o >>= 1) es += __shfl_xor_sync(FULL, es, o);
        float a = e / es;

        if (lane < 12) {
            int l = pp >> 2;
            int S  = (l == 0) ? 24 : ((l == 1) ? 12 : 6);
            int st = (l == 0) ? 0  : ((l == 1) ? NHIGH : NMIDEND);
            const float* o = offaw + (size_t)bq * 288 + h * 36 + pp * 3;
            float pd = rd * S + o[0] - 0.5f;
            float px = rx * S + o[1] - 0.5f;
            float py = ry * S + o[2] - 0.5f;
            float fd = floorf(pd), fx = floorf(px), fy = floorf(py);
            int d0 = (int)fd, x0 = (int)fx, y0 = (int)fy;
            int d1 = d0 + 1, x1 = x0 + 1, y1 = y0 + 1;
            float wd1 = pd - fd, wx1 = px - fx, wy1 = py - fy;
            float wD0 = a * (1.f - wd1) * ((d0 >= 0 && d0 < S) ? 1.f : 0.f);
            float wD1 = a * wd1        * ((d1 >= 0 && d1 < S) ? 1.f : 0.f);
            float wY0 = (1.f - wy1) * ((y0 >= 0 && y0 < S) ? 1.f : 0.f);
            float wY1 = wy1         * ((y1 >= 0 && y1 < S) ? 1.f : 0.f);
            float wX0 = (1.f - wx1) * ((x0 >= 0 && x0 < S) ? 1.f : 0.f);
            float wX1 = wx1         * ((x1 >= 0 && x1 < S) ? 1.f : 0.f);
            int cd0 = min(max(d0, 0), S - 1), cd1 = min(max(d1, 0), S - 1);
            int cy0 = min(max(y0, 0), S - 1), cy1 = min(max(y1, 0), S - 1);
            int cx0 = min(max(x0, 0), S - 1);
            int cx1 = min(max(x1, 0), S - 1);
            int c0b = cx0 * (DIM * 2), c1b = cx1 * (DIM * 2);
            int ib[4];
            ib[0] = (st + cd0 * S * S + cy0 * S) * (DIM * 2);
            ib[1] = (st + cd0 * S * S + cy1 * S) * (DIM * 2);
            ib[2] = (st + cd1 * S * S + cy0 * S) * (DIM * 2);
            ib[3] = (st + cd1 * S * S + cy1 * S) * (DIM * 2);
            float wdy[4];
            wdy[0] = wD0 * wY0; wdy[1] = wD0 * wY1;
            wdy[2] = wD1 * wY0; wdy[3] = wD1 * wY1;
            #pragma unroll
            for (int cg = 0; cg < 4; cg++) {
                float4 ent;
                ent.x = wdy[cg] * wX0;
                ent.y = wdy[cg] * wX1;
                ent.z = __int_as_float(ib[cg] + c0b);
                ent.w = __int_as_float(ib[cg] + c1b);
                s_pt[wslot][pp][cg] = ent;
            }
        }
    }
    __syncwarp();

    // ---- phase 2: per point: 1 LDS.128 + 2 LDG.128, packed f32x2 FMA ----
    const int cg  = lane >> 3;
    const int ch8 = (lane & 7) * 8;
    const char* vbb = (const char*)(value + (size_t)b * NTOK * DIM + h * HDIM + ch8);

    unsigned long long a01 = 0ull, a23 = 0ull, a45 = 0ull, a67 = 0ull;
    #pragma unroll
    for (int p = 0; p < 12; p++) {
        float4 ent = s_pt[wslot][p][cg];
        {
            uint4 raw = *(const uint4*)(vbb + __float_as_int(ent.z));
            unsigned long long w2 = dup_f32x2(ent.x);
            fma_f32x2(a01, pack2_from_bf16x2(raw.x), w2);
            fma_f32x2(a23, pack2_from_bf16x2(raw.y), w2);
            fma_f32x2(a45, pack2_from_bf16x2(raw.z), w2);
            fma_f32x2(a67, pack2_from_bf16x2(raw.w), w2);
        }
        {
            uint4 raw = *(const uint4*)(vbb + __float_as_int(ent.w));
            unsigned long long w2 = dup_f32x2(ent.y);
            fma_f32x2(a01, pack2_from_bf16x2(raw.x), w2);
            fma_f32x2(a23, pack2_from_bf16x2(raw.y), w2);
            fma_f32x2(a45, pack2_from_bf16x2(raw.z), w2);
            fma_f32x2(a67, pack2_from_bf16x2(raw.w), w2);
        }
    }
    float2 p01 = unpack_f32x2(a01);
    float2 p23 = unpack_f32x2(a23);
    float2 p45 = unpack_f32x2(a45);
    float2 p67 = unpack_f32x2(a67);
    float a0 = p01.x, a1 = p01.y, a2 = p23.x, a3 = p23.y;
    float a4 = p45.x, a5 = p45.y, a6 = p67.x, a7 = p67.y;
    #pragma unroll
    for (int o = 16; o >= 8; o >>= 1) {
        a0 += __shfl_down_sync(FULL, a0, o);
        a1 += __shfl_down_sync(FULL, a1, o);
        a2 += __shfl_down_sync(FULL, a2, o);
        a3 += __shfl_down_sync(FULL, a3, o);
        a4 += __shfl_down_sync(FULL, a4, o);
        a5 += __shfl_down_sync(FULL, a5, o);
        a6 += __shfl_down_sync(FULL, a6, o);
        a7 += __shfl_down_sync(FULL, a7, o);
    }
    if (lane < 8) {
        uint4 pkt;
        pkt.x = pack_bf16x2(a0, a1);
        pkt.y = pack_bf16x2(a2, a3);
        pkt.z = pack_bf16x2(a4, a5);
        pkt.w = pack_bf16x2(a6, a7);
        *(uint4*)(out + (size_t)bq * DIM + h * HDIM + ch8) = pkt;
    }
}

// ---------------- depthwise 3x3x3 conv + GELU: 48 voxels/block, 8ch/thread ----
__global__ void __launch_bounds__(576) dwconv_gelu_kernel(
        const bf16* __restrict__ x, const float* __restrict__ w,
        const float* __restrict__ bias, bf16* __restrict__ y)
{
    __shared__ float sw[27 * HID];
    int tid = threadIdx.x;                 // 576
    for (int i = tid; i < 27 * HID; i += 576) sw[i] = w[i];
    __syncthreads();

    int c8  = (tid % 12) * 8;
    int vox = tid / 12;
    int vlin = blockIdx.x * 48 + vox;
    int b = vlin / NTOK, v = vlin % NTOK;

    int S, base;
    if (v < NHIGH)        { S = 24; base = 0; }
    else if (v < NMIDEND) { S = 12; base = NHIGH; }
    else                  { S = 6;  base = NMIDEND; }
    int loc = v - base;
    int d = loc / (S * S), yy = (loc / S) % S, xx = loc % S;

    const bf16* xb = x + ((size_t)b * NTOK + base) * HID + c8;
    float4 bv0 = *(const float4*)&bias[c8];
    float4 bv1 = *(const float4*)&bias[c8 + 4];
    float a0 = bv0.x, a1 = bv0.y, a2 = bv0.z, a3 = bv0.w;
    float a4 = bv1.x, a5 = bv1.y, a6 = bv1.z, a7 = bv1.w;
    #pragma unroll
    for (int kd = 0; kd < 3; kd++) {
        int di = d + kd - 1;
        if (di < 0 || di >= S) continue;
        #pragma unroll
        for (int kh = 0; kh < 3; kh++) {
            int yi = yy + kh - 1;
            if (yi < 0 || yi >= S) continue;
            #pragma unroll
            for (int kw = 0; kw < 3; kw++) {
                int xi = xx + kw - 1;
                if (xi < 0 || xi >= S) continue;
                uint4 raw = *(const uint4*)(xb + (size_t)((di * S + yi) * S + xi) * HID);
                float2 va = __bfloat1622float2(*(const __nv_bfloat162*)&raw.x);
                float2 vb2 = __bfloat1622float2(*(const __nv_bfloat162*)&raw.y);
                float2 vc = __bfloat1622float2(*(const __nv_bfloat162*)&raw.z);
                float2 vd = __bfloat1622float2(*(const __nv_bfloat162*)&raw.w);
                const float* wp = &sw[((kd * 3 + kh) * 3 + kw) * HID + c8];
                float4 wv0 = *(const float4*)wp;
                float4 wv1 = *(const float4*)(wp + 4);
                a0 += wv0.x * va.x;  a1 += wv0.y * va.y;
                a2 += wv0.z * vb2.x; a3 += wv0.w * vb2.y;
                a4 += wv1.x * vc.x;  a5 += wv1.y * vc.y;
                a6 += wv1.z * vd.x;  a7 += wv1.w * vd.y;
            }
        }
    }
    const float ISQ2 = 0.70710678118654752f;
    float g0 = 0.5f * a0 * (1.f + erff(a0 * ISQ2));
    float g1 = 0.5f * a1 * (1.f + erff(a1 * ISQ2));
    float g2 = 0.5f * a2 * (1.f + erff(a2 * ISQ2));
    float g3 = 0.5f * a3 * (1.f + erff(a3 * ISQ2));
    float g4 = 0.5f * a4 * (1.f + erff(a4 * ISQ2));
    float g5 = 0.5f * a5 * (1.f + erff(a5 * ISQ2));
    float g6 = 0.5f * a6 * (1.f + erff(a6 * ISQ2));
    float g7 = 0.5f * a7 * (1.f + erff(a7 * ISQ2));
    uint4 pkt;
    pkt.x = pack_bf16x2(g0, g1);
    pkt.y = pack_bf16x2(g2, g3);
    pkt.z = pack_bf16x2(g4, g5);
    pkt.w = pack_bf16x2(g6, g7);
    *(uint4*)(y + ((size_t)b * NTOK + v) * HID + c8) = pkt;
}

// ---------------- launch ----------------
static void* sym_addr(const void* sym) {
    void* p = nullptr;
    cudaGetSymbolAddress(&p, sym);
    return p;
}

extern "C" void kernel_launch(void* const* d_in, const int* in_sizes, int n_in,
                              void* d_out, int out_size)
{
    const float* query = (const float*)d_in[0];
    const float* feat  = (const float*)d_in[2];
    int wb = n_in - 24;
    const float* qnorm_w    = (const float*)d_in[wb + 0];
    const float* qnorm_b    = (const float*)d_in[wb + 1];
    const float* fnorm_w    = (const float*)d_in[wb + 2];
    const float* fnorm_b    = (const float*)d_in[wb + 3];
    const float* ext_qnorm_w= (const float*)d_in[wb + 4];
    const float* ext_qnorm_b= (const float*)d_in[wb + 5];
    const float* ext_fnorm_w= (const float*)d_in[wb + 6];
    const float* ext_fnorm_b= (const float*)d_in[wb + 7];
    const float* ffn_norm_w = (const float*)d_in[wb + 8];
    const float* ffn_norm_b = (const float*)d_in[wb + 9];
    const float* off_w      = (const float*)d_in[wb + 10];
    const float* off_b      = (const float*)d_in[wb + 11];
    const float* aw_w       = (const float*)d_in[wb + 12];
    const float* aw_b       = (const float*)d_in[wb + 13];
    const float* val_w      = (const float*)d_in[wb + 14];
    const float* val_b      = (const float*)d_in[wb + 15];
    const float* out_w      = (const float*)d_in[wb + 16];
    const float* out_b      = (const float*)d_in[wb + 17];
    const float* fc1_w      = (const float*)d_in[wb + 18];
    const float* fc1_b      = (const float*)d_in[wb + 19];
    const float* dw_w       = (const float*)d_in[wb + 20];
    const float* dw_b       = (const float*)d_in[wb + 21];
    const float* fc2_w      = (const float*)d_in[wb + 22];
    const float* fc2_b      = (const float*)d_in[wb + 23];

    float* qn    = (float*)sym_addr(g_qn);
    float* out1  = (float*)sym_addr(g_out1);
    float* offaw = (float*)sym_addr(g_offaw);
    float* bias288 = (float*)sym_addr(g_bias288);
    bf16* aqb    = (bf16*)sym_addr(g_aq_b);
    bf16* afb    = (bf16*)sym_addr(g_af_b);
    bf16* valb   = (bf16*)sym_addr(g_val_b);
    bf16* doutb  = (bf16*)sym_addr(g_dout_b);
    bf16* xfb    = (bf16*)sym_addr(g_xf_b);
    bf16* xgb    = (bf16*)sym_addr(g_xg_b);
    bf16* wbf    = (bf16*)sym_addr(g_wb);
    float* outp  = (float*)d_out;

    cudaFuncSetAttribute(gemm_bf16_kernel<false, true>,  cudaFuncAttributeMaxDynamicSharedMemorySize, GEMM_SMEM);
    cudaFuncSetAttribute(gemm_bf16_kernel<false, false>, cudaFuncAttributeMaxDynamicSharedMemorySize, GEMM_SMEM);
    cudaFuncSetAttribute(gemm_bf16_kernel<true,  false>, cudaFuncAttributeMaxDynamicSharedMemorySize, GEMM_SMEM);
    cudaFuncSetAttribute(gemm_dual_kernel, cudaFuncAttributeMaxDynamicSharedMemorySize, GEMM_SMEM);

    const int M = MROWS;
    int gy = (M + 127) / 128;
    int grow = (M + 7) / 8;

    // 1) q build + LN chain (warp per row) + fused weight convert
    prep_kernel<<<grow, 256>>>(query, feat, qnorm_w, qnorm_b, fnorm_w, fnorm_b,
                               ext_qnorm_w, ext_qnorm_b, ext_fnorm_w, ext_fnorm_b,
                               qn, aqb, afb,
                               val_w, off_w, aw_w, out_w, fc1_w, fc2_w,
                               off_b, aw_b, wbf, bias288);
    // 2+3) fused: value = af @ val_w + val_b (bf16) AND offaw = aq @ [off|aw]_w + bias (fp32)
    gemm_dual_kernel<<<dim3(7, gy), 256, GEMM_SMEM>>>(
        afb, wbf + WOFF_VAL, val_b, valb, 384,
        aqb, wbf + WOFF_OFFAW, bias288, offaw, 288,
        M, 384, 4);
    // 4) deformable sampling (softmax fused)
    {
        int warps = MROWS * HEADS;
        int blocks = (warps + 7) / 8;
        deform_kernel<<<blocks, 256>>>(offaw, valb, doutb);
    }
    // 5) out1 = qn + dout @ out_w + out_b (fp32)
    gemm_bf16_kernel<true, false><<<dim3(4, gy), 256, GEMM_SMEM>>>(doutb, wbf + WOFF_OUT, out_b, qn, out1, M, 384, 384);
    // 6) t = LN(out1, ffn_norm) -> bf16
    ln_kernel<<<grow, 256>>>(out1, ffn_norm_w, ffn_norm_b, aqb);
    // 7) x = t @ fc1_w + fc1_b  (bf16 out)
    gemm_bf16_kernel<false, true><<<dim3(1, gy), 256, GEMM_SMEM>>>(aqb, wbf + WOFF_FC1, fc1_b, nullptr, xfb, M, 96, 384);
    // 8) depthwise conv + GELU (bf16 out, 48 voxels/block)
    dwconv_gelu_kernel<<<MROWS / 48, 576>>>(xfb, dw_w, dw_b, xgb);
    // 9) out = out1 + xg @ fc2_w + fc2_b (fp32)
    gemm_bf16_kernel<true, false><<<dim3(4, gy), 256, GEMM_SMEM>>>(xgb, wbf + WOFF_FC2, fc2_b, out1, outp, M, 384, 96);
}